// round 17
// baseline (speedup 1.0000x reference)
#include <cuda_runtime.h>
#include <cuda_bf16.h>
#include <math.h>

#define T_OBS 8
#define EPSBN 1e-5f
#define HP_GROUPS 8    // rows per k_hppos block = 8*64 = 512

typedef unsigned int u32;
typedef unsigned long long u64;

#define MAXB 131072
#define WSTR 88   // padded k-stride (bf16): 176B rows, conflict-free ldmatrix

// ---------------- static device scratch ------------------------------------
__device__ float  g_h[MAXB * 64];
__device__ float  g_c[MAXB * 64];
__device__ float  g_last[MAXB * 2];
__device__ __align__(16) __nv_bfloat16 g_Wh[256 * WSTR];
__device__ __align__(16) __nv_bfloat16 g_Wl[256 * WSTR];
__device__ float  g_bias[256];
__device__ double g_enc_stats[5];
__device__ double g_se_stats[5];
__device__ double g_hp_stats[32];
__device__ u32    g_barc = 0;
__device__ u32    g_barg = 0;

// ---------------- helpers ----------------------------------------------------
__device__ __forceinline__ float scalar_f(const void* p) {
    int iv = *(const int*)p;
    float fv = __int_as_float(iv);
    if (fv >= 1e-3f && fv <= 1e7f) return fv;
    return (float)iv;
}
__device__ __forceinline__ float fast_sig(float x) {
    float t; asm("ex2.approx.f32 %0, %1;" : "=f"(t) : "f"(-1.4426950408889634f * x));
    float r; asm("rcp.approx.f32 %0, %1;" : "=f"(r) : "f"(1.0f + t));
    return r;
}
// fused LSTM pointwise: 8 MUFU per cell
__device__ __forceinline__ void lstm_cell(float iv, float fv, float gv, float ov,
                                          float cold, float& cnew, float& hnew) {
    gv = fminf(fmaxf(gv, -30.f), 30.f);
    float tf; asm("ex2.approx.f32 %0, %1;" : "=f"(tf) : "f"(-1.4426950408889634f * fv));
    float sf; asm("rcp.approx.f32 %0, %1;" : "=f"(sf) : "f"(1.0f + tf));
    float ei; asm("ex2.approx.f32 %0, %1;" : "=f"(ei) : "f"(-1.4426950408889634f * iv));
    float eg; asm("ex2.approx.f32 %0, %1;" : "=f"(eg) : "f"(2.8853900817779268f * gv));
    float dig = (1.0f + ei) * (eg + 1.0f);
    float rig; asm("rcp.approx.f32 %0, %1;" : "=f"(rig) : "f"(dig));
    float c2 = sf * cold + (eg - 1.0f) * rig;
    cnew = c2;
    float eo; asm("ex2.approx.f32 %0, %1;" : "=f"(eo) : "f"(-1.4426950408889634f * ov));
    float ec; asm("ex2.approx.f32 %0, %1;" : "=f"(ec) : "f"(2.8853900817779268f * c2));
    float doc = (1.0f + eo) * (ec + 1.0f);
    float roc; asm("rcp.approx.f32 %0, %1;" : "=f"(roc) : "f"(doc));
    hnew = (ec - 1.0f) * roc;
}
__device__ __forceinline__ float wred(float v) {
#pragma unroll
    for (int o = 16; o > 0; o >>= 1) v += __shfl_down_sync(0xffffffffu, v, o);
    return v;
}
__device__ __forceinline__ u32 smem_u32(const void* p) {
    u32 a;
    asm("{ .reg .u64 t; cvta.to.shared.u64 t, %1; cvt.u32.u64 %0, t; }" : "=r"(a) : "l"(p));
    return a;
}
__device__ __forceinline__ void ldsm4(u32* r, u32 addr) {
    asm volatile("ldmatrix.sync.aligned.m8n8.x4.shared.b16 {%0,%1,%2,%3}, [%4];"
        : "=r"(r[0]), "=r"(r[1]), "=r"(r[2]), "=r"(r[3]) : "r"(addr));
}
__device__ __forceinline__ void mma16816(float* d, const u32* a, const u32* b) {
    asm volatile(
        "mma.sync.aligned.m16n8k16.row.col.f32.bf16.bf16.f32 "
        "{%0,%1,%2,%3},{%4,%5,%6,%7},{%8,%9},{%0,%1,%2,%3};"
        : "+f"(d[0]), "+f"(d[1]), "+f"(d[2]), "+f"(d[3])
        : "r"(a[0]), "r"(a[1]), "r"(a[2]), "r"(a[3]), "r"(b[0]), "r"(b[1]));
}
__device__ __forceinline__ u32 pack_bf16_hi(float a0, float a1) {
    __nv_bfloat16 h0 = __float2bfloat16(a0), h1 = __float2bfloat16(a1);
    return ((u32)__bfloat16_as_ushort(h1) << 16) | __bfloat16_as_ushort(h0);
}
__device__ __forceinline__ u32 pack_bf16_lo(float a0, float a1) {
    __nv_bfloat16 h0 = __float2bfloat16(a0), h1 = __float2bfloat16(a1);
    __nv_bfloat16 l0 = __float2bfloat16(a0 - __bfloat162float(h0));
    __nv_bfloat16 l1 = __float2bfloat16(a1 - __bfloat162float(h1));
    return ((u32)__bfloat16_as_ushort(l1) << 16) | __bfloat16_as_ushort(l0);
}
__device__ __forceinline__ double vload(const double* p) {
    return *(volatile const double*)p;
}
__device__ __forceinline__ void grid_barrier() {
    __syncthreads();
    if (threadIdx.x == 0) {
        __threadfence();
        u32 gen = *(volatile u32*)&g_barg;
        u32 old = atomicAdd(&g_barc, 1);
        if (old == gridDim.x - 1) {
            atomicExch(&g_barc, 0);
            __threadfence();
            atomicExch(&g_barg, gen + 1);
        } else {
            while (*(volatile u32*)&g_barg == gen) { __nanosleep(64); }
        }
        __threadfence();
    }
    __syncthreads();
}

// ---------------- smem layouts ------------------------------------------------
#define O_WH   0                    // 45056
#define O_WL   45056                // 45056
// both LSTM kernels: 256 thr, 2 CTA/SM, 32-row tiles, double-buffered A
#define L_AB0  90112                // AH0; AL0=+5632; AH1=+11264; AL1=+16896
#define L_BIAS 112640               // 1024
#define L_FOLD 113664               // 192
#define LSTM_SMEM 113856

// ---------------- prep: fold se_W2/se_b2 into Wih; bf16-split ---------------
__global__ void k_prep(const float* __restrict__ Wih, const float* __restrict__ Whh,
                       const float* __restrict__ bih, const float* __restrict__ bhh,
                       const float* __restrict__ seW2, const float* __restrict__ seb2) {
    int gc = threadIdx.x;
    if (gc < 5) g_enc_stats[gc] = 0.0;
    float wr[64];
#pragma unroll 8
    for (int m = 0; m < 64; m++) wr[m] = Wih[gc * 64 + m];
    float be = bih[gc] + bhh[gc];
#pragma unroll 8
    for (int m = 0; m < 64; m++) be += wr[m] * seb2[m];
    g_bias[gc] = be;
    for (int k = 0; k < WSTR; k++) {
        float w = 0.f;
        if (k < 16) {
#pragma unroll 8
            for (int m = 0; m < 64; m++) w += wr[m] * seW2[m * 16 + k];
        } else if (k < 80) {
            w = Whh[gc * 64 + (k - 16)];
        }
        __nv_bfloat16 hi = __float2bfloat16(w);
        __nv_bfloat16 lo = __float2bfloat16(w - __bfloat162float(hi));
        g_Wh[gc * WSTR + k] = hi;
        g_Wl[gc * WSTR + k] = lo;
    }
}

// ---------------- moments of normalized obs + init last_pos -----------------
__global__ void k_moments(const float* __restrict__ obs, const void* pxm, const void* pym,
                          int TB, int B) {
    __shared__ float red[8][5];
    float invx = 1.0f / scalar_f(pxm), invy = 1.0f / scalar_f(pym);
    int idx = blockIdx.x * blockDim.x + threadIdx.x;
    int stride = gridDim.x * blockDim.x;
    float s[5] = {0, 0, 0, 0, 0};
    for (int i = idx; i < TB; i += stride) {
        float x = obs[2 * i] * invx, y = obs[2 * i + 1] * invy;
        s[0] += x; s[1] += y; s[2] += x * x; s[3] += y * y; s[4] += x * y;
    }
    int wid = threadIdx.x >> 5, lane = threadIdx.x & 31;
#pragma unroll
    for (int k = 0; k < 5; k++) s[k] = wred(s[k]);
    if (lane == 0) {
#pragma unroll
        for (int k = 0; k < 5; k++) red[wid][k] = s[k];
    }
    __syncthreads();
    if (wid == 0 && lane < 5) {
        float t = 0.f;
#pragma unroll
        for (int w = 0; w < 8; w++) t += red[w][lane];
        atomicAdd(&g_enc_stats[lane], (double)t);
    }
    int off = TB - B;
    for (int i = idx; i < B; i += stride) {
        g_last[2 * i]     = obs[2 * (off + i)]     * invx;
        g_last[2 * i + 1] = obs[2 * (off + i) + 1] * invy;
    }
}

// ===== fused 8-step encoder: 256 thr, 32-row tiles, 2 CTAs/SM, dbl-buf A ====
__global__ void __launch_bounds__(256, 2)
k_enc(const float* __restrict__ obs, int B, int nTiles,
      const float* __restrict__ seW1, const float* __restrict__ seb1,
      const float* __restrict__ seg_, const float* __restrict__ seb_,
      const void* pxm, const void* pym, float Ninv) {
    extern __shared__ char sm[];
    float* bs = (float*)(sm + L_BIAS);
    float* fold = (float*)(sm + L_FOLD);
    u32 smb = smem_u32(sm);
    int tid = threadIdx.x, wid = tid >> 5, lane = tid & 31;

    {
        const float4* s1 = (const float4*)g_Wh;
        const float4* s2 = (const float4*)g_Wl;
        float4* d1 = (float4*)(sm + O_WH);
        float4* d2 = (float4*)(sm + O_WL);
        for (int i = tid; i < 2816; i += 256) { d1[i] = s1[i]; d2[i] = s2[i]; }
    }
    bs[tid] = g_bias[tid];
    if (blockIdx.x == 0 && tid < 32) g_hp_stats[tid] = 0.0;
    if (tid < 16) {   // encode BN fold (analytic, from 5 moments)
        const double* st = g_enc_stats;
        double mx = st[0] * Ninv, my = st[1] * Ninv;
        double vxx = st[2] * Ninv - mx * mx;
        double vyy = st[3] * Ninv - my * my;
        double cxy = st[4] * Ninv - mx * my;
        float w0 = seW1[2 * tid], w1 = seW1[2 * tid + 1];
        float mu = (float)(w0 * mx + w1 * my) + seb1[tid];
        float var = (float)((double)w0 * w0 * vxx + (double)w1 * w1 * vyy +
                            2.0 * (double)w0 * w1 * cxy);
        float sc = seg_[tid] * rsqrtf(var + EPSBN);
        float ix = 1.f / scalar_f(pxm), iy = 1.f / scalar_f(pym);
        fold[tid]      = w0 * sc * ix;
        fold[16 + tid] = w1 * sc * iy;
        fold[32 + tid] = (seb1[tid] - mu) * sc + seb_[tid];
    }
    __syncthreads();

    int wn = wid;
    int j0 = wn * 8 + (lane & 3) * 2;
    float bj[4][2];
#pragma unroll
    for (int g = 0; g < 4; g++) { bj[g][0] = bs[g * 64 + j0]; bj[g][1] = bs[g * 64 + j0 + 1]; }

    u32 bh[3][4][2];
    {
        u32 nrow = (u32)(wn * 8 + (lane & 7));
        u32 gsel = (u32)(((lane >> 4) & 1) * 64);
        u32 ksel = (u32)(((lane >> 3) & 1) * 16);
#pragma unroll
        for (int kt = 0; kt < 3; kt++) {
#pragma unroll
            for (int p = 0; p < 2; p++) {
                u32 r4[4];
                ldsm4(r4, smb + O_WH +
                      ((u32)(p * 2) * 64 + gsel + nrow) * (WSTR * 2) + ksel + (u32)(kt * 32));
                bh[kt][2 * p][0] = r4[0]; bh[kt][2 * p][1] = r4[1];
                bh[kt][2 * p + 1][0] = r4[2]; bh[kt][2 * p + 1][1] = r4[3];
            }
        }
    }

    u32 aRowOff = (u32)((lane & 15) * (WSTR * 2));
    u32 aColSel = (u32)(((lane >> 4) & 1) * 16);
    u32 bRow = (u32)(wn * 8 + (lane & 7));
    u32 bGsel = (u32)(((lane >> 4) & 1) * 64);
    u32 bKsel = (u32)(((lane >> 3) & 1) * 16);
    int srow = tid >> 3, seg8 = tid & 7, j2 = seg8 * 2;
    float fa0 = fold[j2], fb0 = fold[16 + j2], fc0 = fold[32 + j2];
    float fa1 = fold[j2 + 1], fb1 = fold[16 + j2 + 1], fc1 = fold[32 + j2 + 1];

    {   // prologue: stage feats t0 of first tile into buf0
        int r = blockIdx.x * 32 + srow;
        float2 xy0 = *(const float2*)(obs + 2 * (size_t)r);
        float f0 = fmaxf(fa0 * xy0.x + fb0 * xy0.y + fc0, 0.f);
        float f1 = fmaxf(fa1 * xy0.x + fb1 * xy0.y + fc1, 0.f);
        int off = srow * (WSTR * 2) + j2 * 2;
        *(u32*)(sm + L_AB0 + off) = pack_bf16_hi(f0, f1);
        *(u32*)(sm + L_AB0 + 5632 + off) = pack_bf16_lo(f0, f1);
    }

    for (int tile = blockIdx.x; tile < nTiles; tile += gridDim.x) {
        int row0 = tile * 32;
        int nxt = tile + gridDim.x;
        float creg[2][2][2];

        for (int t = 0; t < T_OBS; t++) {
            u32 ahb = smb + L_AB0 + (u32)((t & 1) * 11264);
            u32 alb = ahb + 5632;
            float2 nxy = make_float2(0.f, 0.f);
            if (t < T_OBS - 1) {
                nxy = *(const float2*)(obs + (size_t)(t + 1) * B * 2 + 2 * (size_t)(row0 + srow));
            } else if (nxt < nTiles) {
                nxy = *(const float2*)(obs + 2 * (size_t)(nxt * 32 + srow));
            }
            __syncthreads();

            float acc[2][4][4];
#pragma unroll
            for (int mt = 0; mt < 2; mt++)
#pragma unroll
                for (int g = 0; g < 4; g++)
#pragma unroll
                    for (int e = 0; e < 4; e++) acc[mt][g][e] = 0.f;
            int nkt = t ? 5 : 1;
#pragma unroll
            for (int kt = 0; kt < 5; kt++) {
                if (kt >= nkt) break;
                u32 kOff = (u32)(kt * 32);
                u32 ah0[4], ah1[4], al0[4], al1[4];
                u32 aAddr = ahb + aRowOff + aColSel + kOff;
                ldsm4(ah0, aAddr);
                ldsm4(ah1, aAddr + 16 * (WSTR * 2));
                u32 aAddrL = alb + aRowOff + aColSel + kOff;
                ldsm4(al0, aAddrL);
                ldsm4(al1, aAddrL + 16 * (WSTR * 2));
                u32 bl[4][2];
#pragma unroll
                for (int p = 0; p < 2; p++) {
                    u32 r4[4];
                    ldsm4(r4, smb + O_WL +
                          ((u32)(p * 2) * 64 + bGsel + bRow) * (WSTR * 2) + bKsel + kOff);
                    bl[2 * p][0] = r4[0]; bl[2 * p][1] = r4[1];
                    bl[2 * p + 1][0] = r4[2]; bl[2 * p + 1][1] = r4[3];
                }
                if (kt < 3) {
#pragma unroll
                    for (int g = 0; g < 4; g++) {
                        mma16816(acc[0][g], ah0, bh[kt][g]);
                        mma16816(acc[1][g], ah1, bh[kt][g]);
                        mma16816(acc[0][g], al0, bh[kt][g]);
                        mma16816(acc[1][g], al1, bh[kt][g]);
                        mma16816(acc[0][g], ah0, bl[g]);
                        mma16816(acc[1][g], ah1, bl[g]);
                    }
                } else {
                    u32 bhd[4][2];
#pragma unroll
                    for (int p = 0; p < 2; p++) {
                        u32 r4[4];
                        ldsm4(r4, smb + O_WH +
                              ((u32)(p * 2) * 64 + bGsel + bRow) * (WSTR * 2) + bKsel + kOff);
                        bhd[2 * p][0] = r4[0]; bhd[2 * p][1] = r4[1];
                        bhd[2 * p + 1][0] = r4[2]; bhd[2 * p + 1][1] = r4[3];
                    }
#pragma unroll
                    for (int g = 0; g < 4; g++) {
                        mma16816(acc[0][g], ah0, bhd[g]);
                        mma16816(acc[1][g], ah1, bhd[g]);
                        mma16816(acc[0][g], al0, bhd[g]);
                        mma16816(acc[1][g], al1, bhd[g]);
                        mma16816(acc[0][g], ah0, bl[g]);
                        mma16816(acc[1][g], ah1, bl[g]);
                    }
                }
            }

            float hn[2][2][2];
#pragma unroll
            for (int mt = 0; mt < 2; mt++)
#pragma unroll
                for (int rr = 0; rr < 2; rr++)
#pragma unroll
                    for (int cc = 0; cc < 2; cc++) {
                        int e = rr * 2 + cc;
                        float iv = acc[mt][0][e] + bj[0][cc];
                        float fv = acc[mt][1][e] + bj[1][cc];
                        float gv = acc[mt][2][e] + bj[2][cc];
                        float ov = acc[mt][3][e] + bj[3][cc];
                        float cold = t ? creg[mt][rr][cc] : 0.f;
                        lstm_cell(iv, fv, gv, ov, cold, creg[mt][rr][cc], hn[mt][rr][cc]);
                    }

            if (t < T_OBS - 1) {
                u32 ahn = smb + L_AB0 + (u32)(((t + 1) & 1) * 11264);
#pragma unroll
                for (int mt = 0; mt < 2; mt++)
#pragma unroll
                    for (int rr = 0; rr < 2; rr++) {
                        int lrow = mt * 16 + rr * 8 + (lane >> 2);
                        int off = lrow * (WSTR * 2) + (16 + j0) * 2;
                        *(u32*)(ahn - smb + sm + off) = pack_bf16_hi(hn[mt][rr][0], hn[mt][rr][1]);
                        *(u32*)(ahn + 5632 - smb + sm + off) = pack_bf16_lo(hn[mt][rr][0], hn[mt][rr][1]);
                    }
                float f0 = fmaxf(fa0 * nxy.x + fb0 * nxy.y + fc0, 0.f);
                float f1 = fmaxf(fa1 * nxy.x + fb1 * nxy.y + fc1, 0.f);
                int off = srow * (WSTR * 2) + j2 * 2;
                *(u32*)(ahn - smb + sm + off) = pack_bf16_hi(f0, f1);
                *(u32*)(ahn + 5632 - smb + sm + off) = pack_bf16_lo(f0, f1);
            } else {
#pragma unroll
                for (int mt = 0; mt < 2; mt++)
#pragma unroll
                    for (int rr = 0; rr < 2; rr++) {
                        int r = row0 + mt * 16 + rr * 8 + (lane >> 2);
                        *(float2*)(g_h + (size_t)r * 64 + j0) =
                            make_float2(hn[mt][rr][0], hn[mt][rr][1]);
                        *(float2*)(g_c + (size_t)r * 64 + j0) =
                            make_float2(creg[mt][rr][0], creg[mt][rr][1]);
                    }
                if (nxt < nTiles) {
                    float f0 = fmaxf(fa0 * nxy.x + fb0 * nxy.y + fc0, 0.f);
                    float f1 = fmaxf(fa1 * nxy.x + fb1 * nxy.y + fc1, 0.f);
                    int off = srow * (WSTR * 2) + j2 * 2;
                    *(u32*)(sm + L_AB0 + off) = pack_bf16_hi(f0, f1);
                    *(u32*)(sm + L_AB0 + 5632 + off) = pack_bf16_lo(f0, f1);
                }
            }
        }
    }
}

// ======== decode LSTM step: 2 CTAs/SM, double-buffered A, 1 sync/tile =======
__global__ void __launch_bounds__(256, 2)
k_dec(int B, int nTiles,
      const float* __restrict__ seW1, const float* __restrict__ seb1,
      const float* __restrict__ seg_, const float* __restrict__ seb_, float Ninv) {
    extern __shared__ char sm[];
    float* bs = (float*)(sm + L_BIAS);
    float* fold = (float*)(sm + L_FOLD);
    u32 smb = smem_u32(sm);
    int tid = threadIdx.x, wid = tid >> 5, lane = tid & 31;

    {
        const float4* s1 = (const float4*)g_Wh;
        const float4* s2 = (const float4*)g_Wl;
        float4* d1 = (float4*)(sm + O_WH);
        float4* d2 = (float4*)(sm + O_WL);
        for (int i = tid; i < 2816; i += 256) { d1[i] = s1[i]; d2[i] = s2[i]; }
    }
    bs[tid] = g_bias[tid];
    if (blockIdx.x == 0 && tid < 32) g_hp_stats[tid] = 0.0;
    if (tid < 16) {   // decode BN fold from se stats
        const double* st = g_se_stats;
        double mx = st[0] * Ninv, my = st[1] * Ninv;
        double vxx = st[2] * Ninv - mx * mx;
        double vyy = st[3] * Ninv - my * my;
        double cxy = st[4] * Ninv - mx * my;
        float w0 = seW1[2 * tid], w1 = seW1[2 * tid + 1];
        float mu = (float)(w0 * mx + w1 * my) + seb1[tid];
        float var = (float)((double)w0 * w0 * vxx + (double)w1 * w1 * vyy +
                            2.0 * (double)w0 * w1 * cxy);
        float sc = seg_[tid] * rsqrtf(var + EPSBN);
        fold[tid]      = w0 * sc;
        fold[16 + tid] = w1 * sc;
        fold[32 + tid] = (seb1[tid] - mu) * sc + seb_[tid];
    }
    __syncthreads();

    int wn = wid;
    int j0 = wn * 8 + (lane & 3) * 2;
    float bj[4][2];
#pragma unroll
    for (int g = 0; g < 4; g++) { bj[g][0] = bs[g * 64 + j0]; bj[g][1] = bs[g * 64 + j0 + 1]; }

    u32 bh[3][4][2];
    {
        u32 nrow = (u32)(wn * 8 + (lane & 7));
        u32 gsel = (u32)(((lane >> 4) & 1) * 64);
        u32 ksel = (u32)(((lane >> 3) & 1) * 16);
#pragma unroll
        for (int kt = 0; kt < 3; kt++) {
#pragma unroll
            for (int p = 0; p < 2; p++) {
                u32 r4[4];
                ldsm4(r4, smb + O_WH +
                      ((u32)(p * 2) * 64 + gsel + nrow) * (WSTR * 2) + ksel + (u32)(kt * 32));
                bh[kt][2 * p][0] = r4[0]; bh[kt][2 * p][1] = r4[1];
                bh[kt][2 * p + 1][0] = r4[2]; bh[kt][2 * p + 1][1] = r4[3];
            }
        }
    }

    u32 aRowOff = (u32)((lane & 15) * (WSTR * 2));
    u32 aColSel = (u32)(((lane >> 4) & 1) * 16);
    u32 bRow = (u32)(wn * 8 + (lane & 7));
    u32 bGsel = (u32)(((lane >> 4) & 1) * 64);
    u32 bKsel = (u32)(((lane >> 3) & 1) * 16);
    int srow = tid >> 3, seg8 = tid & 7, j2 = seg8 * 2;
    float fa0 = fold[j2], fb0 = fold[16 + j2], fc0 = fold[32 + j2];
    float fa1 = fold[j2 + 1], fb1 = fold[16 + j2 + 1], fc1 = fold[32 + j2 + 1];

    {   // prologue: stage first 32-row tile into buf0
        int r = blockIdx.x * 32 + srow;
        const float4* hp = (const float4*)(g_h + (size_t)r * 64 + seg8 * 8);
        float4 h0 = hp[0], h1 = hp[1];
        float2 lp = *(const float2*)(g_last + 2 * (size_t)r);
        uint4 hi, lo;
        hi.x = pack_bf16_hi(h0.x, h0.y); lo.x = pack_bf16_lo(h0.x, h0.y);
        hi.y = pack_bf16_hi(h0.z, h0.w); lo.y = pack_bf16_lo(h0.z, h0.w);
        hi.z = pack_bf16_hi(h1.x, h1.y); lo.z = pack_bf16_lo(h1.x, h1.y);
        hi.w = pack_bf16_hi(h1.z, h1.w); lo.w = pack_bf16_lo(h1.z, h1.w);
        int off = srow * (WSTR * 2) + 32 + seg8 * 16;
        *(uint4*)(sm + L_AB0 + off) = hi;
        *(uint4*)(sm + L_AB0 + 5632 + off) = lo;
        float f0 = fmaxf(fa0 * lp.x + fb0 * lp.y + fc0, 0.f);
        float f1 = fmaxf(fa1 * lp.x + fb1 * lp.y + fc1, 0.f);
        int offf = srow * (WSTR * 2) + j2 * 2;
        *(u32*)(sm + L_AB0 + offf) = pack_bf16_hi(f0, f1);
        *(u32*)(sm + L_AB0 + 5632 + offf) = pack_bf16_lo(f0, f1);
    }

    int pbuf = 0;
    for (int tile = blockIdx.x; tile < nTiles; tile += gridDim.x) {
        int row0 = tile * 32;
        int nxt = tile + gridDim.x;
        u32 ahb = smb + L_AB0 + (u32)(pbuf * 11264);
        u32 alb = ahb + 5632;

        float4 nh0, nh1; float2 nlp;
        bool hasNext = (nxt < nTiles);
        if (hasNext) {
            int r = nxt * 32 + srow;
            const float4* hp = (const float4*)(g_h + (size_t)r * 64 + seg8 * 8);
            nh0 = hp[0]; nh1 = hp[1];
            nlp = *(const float2*)(g_last + 2 * (size_t)r);
        }
        float2 cpre[2][2];
#pragma unroll
        for (int mt = 0; mt < 2; mt++)
#pragma unroll
            for (int rr = 0; rr < 2; rr++) {
                int rw = row0 + mt * 16 + rr * 8 + (lane >> 2);
                cpre[mt][rr] = *(const float2*)(g_c + (size_t)rw * 64 + j0);
            }
        __syncthreads();

        float acc[2][4][4];
#pragma unroll
        for (int mt = 0; mt < 2; mt++)
#pragma unroll
            for (int g = 0; g < 4; g++)
#pragma unroll
                for (int e = 0; e < 4; e++) acc[mt][g][e] = 0.f;

#pragma unroll
        for (int kt = 0; kt < 5; kt++) {
            u32 kOff = (u32)(kt * 32);
            u32 ah0[4], ah1[4], al0[4], al1[4];
            u32 aAddr = ahb + aRowOff + aColSel + kOff;
            ldsm4(ah0, aAddr);
            ldsm4(ah1, aAddr + 16 * (WSTR * 2));
            u32 aAddrL = alb + aRowOff + aColSel + kOff;
            ldsm4(al0, aAddrL);
            ldsm4(al1, aAddrL + 16 * (WSTR * 2));
            u32 bl[4][2];
#pragma unroll
            for (int p = 0; p < 2; p++) {
                u32 r4[4];
                ldsm4(r4, smb + O_WL +
                      ((u32)(p * 2) * 64 + bGsel + bRow) * (WSTR * 2) + bKsel + kOff);
                bl[2 * p][0] = r4[0]; bl[2 * p][1] = r4[1];
                bl[2 * p + 1][0] = r4[2]; bl[2 * p + 1][1] = r4[3];
            }
            if (kt < 3) {
#pragma unroll
                for (int g = 0; g < 4; g++) {
                    mma16816(acc[0][g], ah0, bh[kt][g]);
                    mma16816(acc[1][g], ah1, bh[kt][g]);
                    mma16816(acc[0][g], al0, bh[kt][g]);
                    mma16816(acc[1][g], al1, bh[kt][g]);
                    mma16816(acc[0][g], ah0, bl[g]);
                    mma16816(acc[1][g], ah1, bl[g]);
                }
            } else {
                u32 bhd[4][2];
#pragma unroll
                for (int p = 0; p < 2; p++) {
                    u32 r4[4];
                    ldsm4(r4, smb + O_WH +
                          ((u32)(p * 2) * 64 + bGsel + bRow) * (WSTR * 2) + bKsel + kOff);
                    bhd[2 * p][0] = r4[0]; bhd[2 * p][1] = r4[1];
                    bhd[2 * p + 1][0] = r4[2]; bhd[2 * p + 1][1] = r4[3];
                }
#pragma unroll
                for (int g = 0; g < 4; g++) {
                    mma16816(acc[0][g], ah0, bhd[g]);
                    mma16816(acc[1][g], ah1, bhd[g]);
                    mma16816(acc[0][g], al0, bhd[g]);
                    mma16816(acc[1][g], al1, bhd[g]);
                    mma16816(acc[0][g], ah0, bl[g]);
                    mma16816(acc[1][g], ah1, bl[g]);
                }
            }
        }

        // stage next tile into the OTHER buffer NOW (overlaps MUFU epilogue)
        if (hasNext) {
            u32 off1 = (u32)(L_AB0 + (pbuf ^ 1) * 11264);
            uint4 hi, lo;
            hi.x = pack_bf16_hi(nh0.x, nh0.y); lo.x = pack_bf16_lo(nh0.x, nh0.y);
            hi.y = pack_bf16_hi(nh0.z, nh0.w); lo.y = pack_bf16_lo(nh0.z, nh0.w);
            hi.z = pack_bf16_hi(nh1.x, nh1.y); lo.z = pack_bf16_lo(nh1.x, nh1.y);
            hi.w = pack_bf16_hi(nh1.z, nh1.w); lo.w = pack_bf16_lo(nh1.z, nh1.w);
            int off = srow * (WSTR * 2) + 32 + seg8 * 16;
            *(uint4*)(sm + off1 + off) = hi;
            *(uint4*)(sm + off1 + 5632 + off) = lo;
            float f0 = fmaxf(fa0 * nlp.x + fb0 * nlp.y + fc0, 0.f);
            float f1 = fmaxf(fa1 * nlp.x + fb1 * nlp.y + fc1, 0.f);
            int offf = srow * (WSTR * 2) + j2 * 2;
            *(u32*)(sm + off1 + offf) = pack_bf16_hi(f0, f1);
            *(u32*)(sm + off1 + 5632 + offf) = pack_bf16_lo(f0, f1);
        }

        // epilogue: pointwise -> global h, c (c was prefetched)
#pragma unroll
        for (int mt = 0; mt < 2; mt++)
#pragma unroll
            for (int rr = 0; rr < 2; rr++) {
                int rw = row0 + mt * 16 + rr * 8 + (lane >> 2);
                float2 c2 = cpre[mt][rr];
                float cn[2], hn[2];
#pragma unroll
                for (int cc = 0; cc < 2; cc++) {
                    int e = rr * 2 + cc;
                    float iv = acc[mt][0][e] + bj[0][cc];
                    float fv = acc[mt][1][e] + bj[1][cc];
                    float gv = acc[mt][2][e] + bj[2][cc];
                    float ov = acc[mt][3][e] + bj[3][cc];
                    lstm_cell(iv, fv, gv, ov, cc ? c2.y : c2.x, cn[cc], hn[cc]);
                }
                *(float2*)(g_c + (size_t)rw * 64 + j0) = make_float2(cn[0], cn[1]);
                *(float2*)(g_h + (size_t)rw * 64 + j0) = make_float2(hn[0], hn[1]);
            }
        pbuf ^= 1;
    }
}

// ===== fused hidden2pos v2: coalesced smem-staged z-proj + barrier + pos ====
__global__ void __launch_bounds__(256, 2)
k_hppos(const float* __restrict__ hpW1, const float* __restrict__ hpb1,
        const float* __restrict__ hpW2, const float* __restrict__ hpb2,
        const float* __restrict__ gamma, const float* __restrict__ beta,
        float* __restrict__ out, const void* pxm, const void* pym,
        float Binv, int B) {
    __shared__ float smh[64 * 68];      // h tile, pad 68: conflict-free LDS.128
    __shared__ float4 Wt4[64 * 4];      // transposed W1: Wt4[k*4+jq] = W[j0..j0+3][k]
    __shared__ float red[8][32];
    __shared__ float scp[34];
    int tid = threadIdx.x, wid = tid >> 5, lane = tid & 31;
    int jq = tid & 3, rloc = tid >> 2;

    for (int i = tid; i < 1024; i += 256) {
        int j = i >> 6, k = i & 63;
        ((float*)Wt4)[k * 16 + j] = hpW1[i];
    }
    if (blockIdx.x == 0 && tid < 5) g_se_stats[tid] = 0.0;
    float b1r[4], w2xr[4], w2yr[4];
#pragma unroll
    for (int i = 0; i < 4; i++) {
        b1r[i] = __ldg(hpb1 + jq * 4 + i);
        w2xr[i] = __ldg(hpW2 + jq * 4 + i);
        w2yr[i] = __ldg(hpW2 + 16 + jq * 4 + i);
    }
    int rbase0 = blockIdx.x * (HP_GROUPS * 64);

    // ---- phase 1: z projection with coalesced loads + hp stats ----
    float z[HP_GROUPS][4];
    float sv[4] = {0, 0, 0, 0}, qv[4] = {0, 0, 0, 0};
#pragma unroll
    for (int g = 0; g < HP_GROUPS; g++) {
        int rbase = rbase0 + g * 64;
        __syncthreads();   // previous group's smh reads done (also orders Wt4 at g=0)
        const float4* src = (const float4*)(g_h + (size_t)rbase * 64);
#pragma unroll
        for (int q = 0; q < 4; q++) {
            int li = q * 256 + tid;
            float4 v = src[li];
            *(float4*)(smh + (li >> 4) * 68 + (li & 15) * 4) = v;
        }
        __syncthreads();
        const float* hr = smh + rloc * 68;
        float zz0 = b1r[0], zz1 = b1r[1], zz2 = b1r[2], zz3 = b1r[3];
#pragma unroll
        for (int k = 0; k < 64; k += 4) {
            float4 h4 = *(const float4*)(hr + k);
            float4 w0 = Wt4[(k + 0) * 4 + jq];
            float4 w1 = Wt4[(k + 1) * 4 + jq];
            float4 w2 = Wt4[(k + 2) * 4 + jq];
            float4 w3 = Wt4[(k + 3) * 4 + jq];
            zz0 += h4.x * w0.x + h4.y * w1.x + h4.z * w2.x + h4.w * w3.x;
            zz1 += h4.x * w0.y + h4.y * w1.y + h4.z * w2.y + h4.w * w3.y;
            zz2 += h4.x * w0.z + h4.y * w1.z + h4.z * w2.z + h4.w * w3.z;
            zz3 += h4.x * w0.w + h4.y * w1.w + h4.z * w2.w + h4.w * w3.w;
        }
        z[g][0] = zz0; z[g][1] = zz1; z[g][2] = zz2; z[g][3] = zz3;
        sv[0] += zz0; sv[1] += zz1; sv[2] += zz2; sv[3] += zz3;
        qv[0] += zz0 * zz0; qv[1] += zz1 * zz1; qv[2] += zz2 * zz2; qv[3] += zz3 * zz3;
    }
    // stats reduce: lanes with same jq (xor 4, 8, 16)
#pragma unroll
    for (int i = 0; i < 4; i++) {
        sv[i] += __shfl_xor_sync(0xffffffffu, sv[i], 4);
        sv[i] += __shfl_xor_sync(0xffffffffu, sv[i], 8);
        sv[i] += __shfl_xor_sync(0xffffffffu, sv[i], 16);
        qv[i] += __shfl_xor_sync(0xffffffffu, qv[i], 4);
        qv[i] += __shfl_xor_sync(0xffffffffu, qv[i], 8);
        qv[i] += __shfl_xor_sync(0xffffffffu, qv[i], 16);
    }
    __syncthreads();
    if (lane < 4) {
#pragma unroll
        for (int i = 0; i < 4; i++) {
            red[wid][lane * 4 + i] = sv[i];
            red[wid][16 + lane * 4 + i] = qv[i];
        }
    }
    __syncthreads();
    if (tid < 32) {
        float t = 0.f;
#pragma unroll
        for (int w = 0; w < 8; w++) t += red[w][tid];
        atomicAdd(&g_hp_stats[tid], (double)t);
    }

    grid_barrier();

    // ---- phase 2: BN fold + positions + se moments ----
    if (tid < 16) {
        int j = tid;
        double mu = vload(&g_hp_stats[j]) * Binv;
        double var = vload(&g_hp_stats[16 + j]) * Binv - mu * mu;
        float s = gamma[j] * rsqrtf((float)var + EPSBN);
        scp[j] = s;
        scp[16 + j] = beta[j] - (float)mu * s;
    }
    if (tid == 16) { scp[32] = hpb2[0]; scp[33] = hpb2[1]; }
    __syncthreads();
    float sc_[4], sh_[4];
#pragma unroll
    for (int i = 0; i < 4; i++) { sc_[i] = scp[jq * 4 + i]; sh_[i] = scp[16 + jq * 4 + i]; }
    float b2x = scp[32], b2y = scp[33];
    float xmax = scalar_f(pxm), ymax = scalar_f(pym);
    float se[5] = {0, 0, 0, 0, 0};
#pragma unroll
    for (int g = 0; g < HP_GROUPS; g++) {
        int r = rbase0 + g * 64 + rloc;
        float px = 0.f, py = 0.f;
#pragma unroll
        for (int i = 0; i < 4; i++) {
            float t = fmaxf(z[g][i] * sc_[i] + sh_[i], 0.f);
            px += t * w2xr[i];
            py += t * w2yr[i];
        }
        px += __shfl_xor_sync(0xffffffffu, px, 1);
        px += __shfl_xor_sync(0xffffffffu, px, 2);
        py += __shfl_xor_sync(0xffffffffu, py, 1);
        py += __shfl_xor_sync(0xffffffffu, py, 2);
        if (jq == 0) {
            float2 lp = *(const float2*)(g_last + 2 * (size_t)r);
            float lx = fast_sig(px + b2x + lp.x);
            float ly = fast_sig(py + b2y + lp.y);
            *(float2*)(g_last + 2 * (size_t)r) = make_float2(lx, ly);
            *(float2*)(out + 2 * (size_t)r) = make_float2(lx * xmax, ly * ymax);
            se[0] += lx; se[1] += ly; se[2] += lx * lx; se[3] += ly * ly; se[4] += lx * ly;
        }
    }
#pragma unroll
    for (int k = 0; k < 5; k++) {
        se[k] += __shfl_xor_sync(0xffffffffu, se[k], 4);
        se[k] += __shfl_xor_sync(0xffffffffu, se[k], 8);
        se[k] += __shfl_xor_sync(0xffffffffu, se[k], 16);
    }
    __syncthreads();
    if (lane == 0) {
#pragma unroll
        for (int k = 0; k < 5; k++) red[wid][k] = se[k];
    }
    __syncthreads();
    if (wid == 0 && lane < 5) {
        float t = 0.f;
#pragma unroll
        for (int w = 0; w < 8; w++) t += red[w][lane];
        atomicAdd(&g_se_stats[lane], (double)t);
    }
}

// ---------------- launch ------------------------------------------------------
extern "C" void kernel_launch(void* const* d_in, const int* in_sizes, int n_in,
                              void* d_out, int out_size) {
    const float* obs  = (const float*)d_in[0];
    const float* seW1 = (const float*)d_in[1];
    const float* seb1 = (const float*)d_in[2];
    const float* seg  = (const float*)d_in[3];
    const float* seb  = (const float*)d_in[4];
    const float* seW2 = (const float*)d_in[5];
    const float* seb2 = (const float*)d_in[6];
    const float* hpW1 = (const float*)d_in[7];
    const float* hpb1 = (const float*)d_in[8];
    const float* hpg  = (const float*)d_in[9];
    const float* hpb  = (const float*)d_in[10];
    const float* hpW2 = (const float*)d_in[11];
    const float* hpb2 = (const float*)d_in[12];
    const float* Wih  = (const float*)d_in[13];
    const float* Whh  = (const float*)d_in[14];
    const float* bih  = (const float*)d_in[15];
    const float* bhh  = (const float*)d_in[16];
    const void*  pxm  = d_in[17];
    const void*  pym  = d_in[18];

    int B = in_sizes[0] / (T_OBS * 2);
    int TB = T_OBS * B;
    int predLen = out_size / (2 * B);
    float* out = (float*)d_out;

    cudaFuncSetAttribute(k_enc, cudaFuncAttributeMaxDynamicSharedMemorySize, LSTM_SMEM);
    cudaFuncSetAttribute(k_dec, cudaFuncAttributeMaxDynamicSharedMemorySize, LSTM_SMEM);

    k_prep<<<1, 256>>>(Wih, Whh, bih, bhh, seW2, seb2);
    k_moments<<<512, 256>>>(obs, pxm, pym, TB, B);
    k_enc<<<296, 256, LSTM_SMEM>>>(obs, B, B / 32, seW1, seb1, seg, seb,
                                   pxm, pym, 1.0f / (float)TB);

    for (int s = 0; s < predLen; s++) {
        k_hppos<<<B / (HP_GROUPS * 64), 256>>>(hpW1, hpb1, hpW2, hpb2, hpg, hpb,
                                               out + (size_t)s * B * 2, pxm, pym,
                                               1.0f / (float)B, B);
        if (s + 1 < predLen)
            k_dec<<<296, 256, LSTM_SMEM>>>(B, B / 32, seW1, seb1, seg, seb,
                                           1.0f / (float)B);
    }
}